// round 5
// baseline (speedup 1.0000x reference)
#include <cuda_runtime.h>
#include <cstdint>
#include <math.h>

#define Bsz 64
#define TT  512
#define Din 256
#define Hh  512
#define G   2048   /* 4*H */

typedef unsigned long long ull;

// ---------------- scratch (static device globals; no allocation) ----------------
// gx layouts are [t][b][4H] (layer0 additionally [d] major) so scan-side reads are
// per-(t) blocks and SGEMM epilogue writes stay coalesced with row order m=(t,b).
__device__ float g_gx0 [(size_t)2*TT*Bsz*G];    // 512 MB
__device__ float g_out0[(size_t)TT*Bsz*2*Hh];   // 128 MB  [t][b][2H]
__device__ float g_gx1f[(size_t)TT*Bsz*G];      // 256 MB  [t][b][4H]
__device__ float g_gx1b[Bsz*G];                 // layer1 bwd projection at t=T-1
__device__ float g_h0[2][2][Bsz*Hh];            // ping-pong h, layer0, per dir
__device__ float g_h1[2][Bsz*Hh];               // ping-pong h, layer1 fwd
__device__ float g_hb[Bsz*Hh];                  // layer1 bwd one-step hidden
__device__ unsigned g_bar[4];                   // {cnt0, gen0, cnt1, gen1}

// ---------------- packed f32x2 helpers ----------------
__device__ __forceinline__ ull ffma2(ull a, ull b, ull c) {
    ull d; asm("fma.rn.f32x2 %0, %1, %2, %3;" : "=l"(d) : "l"(a), "l"(b), "l"(c)); return d;
}
__device__ __forceinline__ float2 unpack2(ull v) {
    float2 f; asm("mov.b64 {%0, %1}, %2;" : "=f"(f.x), "=f"(f.y) : "l"(v)); return f;
}
__device__ __forceinline__ float sigf(float x) { return 1.0f / (1.0f + expf(-x)); }

// ---------------- software grid barrier (cooperative-groups pattern) ----------------
__device__ __forceinline__ void grid_bar(unsigned* cnt, unsigned* gen,
                                         unsigned target, unsigned nCTA) {
    volatile unsigned* vgen = (volatile unsigned*)gen;
    __syncthreads();
    if (threadIdx.x == 0) {
        __threadfence();
        unsigned prev = atomicAdd(cnt, 1u);
        if (prev + 1u == nCTA * target) {
            __threadfence();
            *vgen = target;
        } else {
            while (*vgen < target) { }
        }
        __threadfence();
    }
    __syncthreads();
}

// ---------------- init (graph replays must be deterministic) ----------------
__global__ void k_init() {
    int i = blockIdx.x * 256 + threadIdx.x;
    if (i < 2*2*Bsz*Hh) (&g_h0[0][0][0])[i] = 0.0f;
    if (i < 2*Bsz*Hh)   (&g_h1[0][0])[i]    = 0.0f;
    if (i < 4)          g_bar[i] = 0u;
}

// ---------------- fp32 SGEMM: C[M,N] = A[M,K] @ Bw[N,K]^T + bia + bib ----------------
// 128x128 tile, BK=8, 256 threads, 8x8 microtile (f32x2), register prefetch of next tile.
// amap=1: logical row m decodes as (t = m>>6, b = m&63) with A row base (b*TT + t)*lda.
__global__ void __launch_bounds__(256) k_sgemm_bias(
    const float* __restrict__ A, int lda, int amap,
    const float* __restrict__ Bw,
    const float* __restrict__ bia, const float* __restrict__ bib,
    float* __restrict__ C, int M, int N, int K)
{
    __shared__ float As[8][128];
    __shared__ float Bs[8][128];
    const int tid = threadIdx.x;
    const int bm = blockIdx.y << 7, bn = blockIdx.x << 7;
    const int lr = tid >> 1, lc = (tid & 1) << 2;
    const int tr = tid >> 4, tc = tid & 15;

    const int am = bm + lr;
    const float* arow;
    if (amap) arow = A + ((size_t)(am & 63) * TT + (size_t)(am >> 6)) * lda;
    else      arow = A + (size_t)am * lda;
    const bool aval = (am < M);
    const float* brow = Bw + (size_t)(bn + lr) * K;

    ull acc[8][4];
#pragma unroll
    for (int i = 0; i < 8; i++)
#pragma unroll
        for (int jj = 0; jj < 4; jj++) acc[i][jj] = 0ull;

    float4 av = aval ? *reinterpret_cast<const float4*>(arow + lc)
                     : make_float4(0.f, 0.f, 0.f, 0.f);
    float4 bv = *reinterpret_cast<const float4*>(brow + lc);

    for (int k0 = 0; k0 < K; k0 += 8) {
        As[lc+0][lr] = av.x; As[lc+1][lr] = av.y; As[lc+2][lr] = av.z; As[lc+3][lr] = av.w;
        Bs[lc+0][lr] = bv.x; Bs[lc+1][lr] = bv.y; Bs[lc+2][lr] = bv.z; Bs[lc+3][lr] = bv.w;
        __syncthreads();

        float4 av2 = av, bv2 = bv;
        if (k0 + 8 < K) {
            av2 = aval ? *reinterpret_cast<const float4*>(arow + k0 + 8 + lc)
                       : make_float4(0.f, 0.f, 0.f, 0.f);
            bv2 = *reinterpret_cast<const float4*>(brow + k0 + 8 + lc);
        }

#pragma unroll
        for (int kk = 0; kk < 8; kk++) {
            float4 a0 = *reinterpret_cast<const float4*>(&As[kk][tr << 3]);
            float4 a1 = *reinterpret_cast<const float4*>(&As[kk][(tr << 3) + 4]);
            const ull* bp = reinterpret_cast<const ull*>(&Bs[kk][tc << 3]);
            ull b0 = bp[0], b1 = bp[1], b2v = bp[2], b3 = bp[3];
            float aarr[8] = {a0.x, a0.y, a0.z, a0.w, a1.x, a1.y, a1.z, a1.w};
#pragma unroll
            for (int i = 0; i < 8; i++) {
                ull a2; asm("mov.b64 %0, {%1, %1};" : "=l"(a2) : "f"(aarr[i]));
                acc[i][0] = ffma2(a2, b0,  acc[i][0]);
                acc[i][1] = ffma2(a2, b1,  acc[i][1]);
                acc[i][2] = ffma2(a2, b2v, acc[i][2]);
                acc[i][3] = ffma2(a2, b3,  acc[i][3]);
            }
        }
        __syncthreads();
        av = av2; bv = bv2;
    }

#pragma unroll
    for (int i = 0; i < 8; i++) {
        int row = bm + (tr << 3) + i;
        if (row >= M) continue;
#pragma unroll
        for (int jj = 0; jj < 4; jj++) {
            float2 p = unpack2(acc[i][jj]);
            int n0 = bn + (tc << 3) + jj * 2;
            C[(size_t)row * N + n0]     = p.x + bia[n0]     + bib[n0];
            C[(size_t)row * N + n0 + 1] = p.y + bia[n0 + 1] + bib[n0 + 1];
        }
    }
}

// ---------------- persistent LSTM scan ----------------
// CTA owns 8 hidden units (warp = 1 unit) and NB=32*NH batches. Weights resident in
// smem for all 512 steps; h staged per step in 4 double-buffered 128-k chunks
// (LDG overlapped with FMA); cell state c in registers; f32x2 accumulation over
// k-parity (no packs); gate pre-activations prefetched at step start; software
// grid barrier between steps. 128 CTAs, 1 CTA/SM -> co-resident (no deadlock).
template<int NH, bool HASOUT>
__device__ __forceinline__ void scan_body(
    int jbase, int bfirst, int rev, int out_off,
    const float* __restrict__ W,      // [2048][512] this direction
    const float* __restrict__ gx,     // [t][b][4H]
    float* __restrict__ hA, float* __restrict__ hB,   // ping-pong [b][H]
    unsigned* barcnt, unsigned* bargen)
{
    constexpr int NB = 32 * NH;
    constexpr int U  = NB / 8;        // float4 per thread per 128-k chunk
    extern __shared__ float sm[];
    float* wsm = sm;                  // [8 warps][4 gates][512 k]
    float* hch = sm + 16384;          // 2 chunk buffers: [NB][132]

    const int tid  = threadIdx.x;
    const int w    = tid >> 5, lane = tid & 31;
    const int j    = jbase + w;

    // stage weights once (k-contiguous rows, direct copy)
    for (int idx = tid; idx < 4096; idx += 256) {
        int ww = idx >> 9;
        int gg = (idx >> 7) & 3;
        int q  = (idx & 127) << 2;
        float4 v = *reinterpret_cast<const float4*>(
            W + ((size_t)(gg * Hh + jbase + ww)) * Hh + q);
        *reinterpret_cast<float4*>(wsm + (((ww << 2) + gg) << 9) + q) = v;
    }

    float creg[NH];
#pragma unroll
    for (int hf = 0; hf < NH; hf++) creg[hf] = 0.0f;

    const float* wb_base = wsm + ((w << 2) << 9);

    for (int t = 0; t < TT; t++) {
        const int tt = rev ? (TT - 1 - t) : t;
        const float* hin  = (t & 1) ? hB : hA;
        float*       hout = (t & 1) ? hA : hB;

        // prefetch gate pre-activations (consumed after the k loop)
        float pre[NH][4];
#pragma unroll
        for (int hf = 0; hf < NH; hf++) {
            int b = bfirst + lane + hf * 32;
            const float* gp = gx + ((size_t)tt * Bsz + b) * G + j;
            pre[hf][0] = gp[0];
            pre[hf][1] = gp[Hh];
            pre[hf][2] = gp[2 * Hh];
            pre[hf][3] = gp[3 * Hh];
        }

        ull acc[NH][4];
#pragma unroll
        for (int hf = 0; hf < NH; hf++)
#pragma unroll
            for (int gg = 0; gg < 4; gg++) acc[hf][gg] = 0ull;

        // stage chunk 0
        {
            float4 pf[U];
#pragma unroll
            for (int u = 0; u < U; u++) {
                int idx = tid + u * 256;
                int r = idx >> 5, kq = (idx & 31) << 2;
                pf[u] = *reinterpret_cast<const float4*>(
                    hin + (size_t)(bfirst + r) * Hh + kq);
            }
#pragma unroll
            for (int u = 0; u < U; u++) {
                int idx = tid + u * 256;
                int r = idx >> 5, kq = (idx & 31) << 2;
                *reinterpret_cast<float4*>(hch + r * 132 + kq) = pf[u];
            }
        }
        __syncthreads();

        int buf = 0;
#pragma unroll
        for (int c = 0; c < 4; c++) {
            float4 pf[U];
            if (c < 3) {
#pragma unroll
                for (int u = 0; u < U; u++) {
                    int idx = tid + u * 256;
                    int r = idx >> 5, kq = (idx & 31) << 2;
                    pf[u] = *reinterpret_cast<const float4*>(
                        hin + (size_t)(bfirst + r) * Hh + (c + 1) * 128 + kq);
                }
            }
            const float* bp = hch + buf * (NB * 132);
            const float* wb = wb_base + c * 128;
#pragma unroll 8
            for (int kk = 0; kk < 128; kk += 4) {
                ulonglong2 wv0 = *reinterpret_cast<const ulonglong2*>(wb + 0 * 512 + kk);
                ulonglong2 wv1 = *reinterpret_cast<const ulonglong2*>(wb + 1 * 512 + kk);
                ulonglong2 wv2 = *reinterpret_cast<const ulonglong2*>(wb + 2 * 512 + kk);
                ulonglong2 wv3 = *reinterpret_cast<const ulonglong2*>(wb + 3 * 512 + kk);
#pragma unroll
                for (int hf = 0; hf < NH; hf++) {
                    ulonglong2 hv = *reinterpret_cast<const ulonglong2*>(
                        bp + (lane + hf * 32) * 132 + kk);
                    acc[hf][0] = ffma2(hv.x, wv0.x, acc[hf][0]);
                    acc[hf][1] = ffma2(hv.x, wv1.x, acc[hf][1]);
                    acc[hf][2] = ffma2(hv.x, wv2.x, acc[hf][2]);
                    acc[hf][3] = ffma2(hv.x, wv3.x, acc[hf][3]);
                    acc[hf][0] = ffma2(hv.y, wv0.y, acc[hf][0]);
                    acc[hf][1] = ffma2(hv.y, wv1.y, acc[hf][1]);
                    acc[hf][2] = ffma2(hv.y, wv2.y, acc[hf][2]);
                    acc[hf][3] = ffma2(hv.y, wv3.y, acc[hf][3]);
                }
            }
            if (c < 3) {
                float* dst = hch + (buf ^ 1) * (NB * 132);
#pragma unroll
                for (int u = 0; u < U; u++) {
                    int idx = tid + u * 256;
                    int r = idx >> 5, kq = (idx & 31) << 2;
                    *reinterpret_cast<float4*>(dst + r * 132 + kq) = pf[u];
                }
            }
            __syncthreads();
            buf ^= 1;
        }

        // gates + state update (c stays in registers)
#pragma unroll
        for (int hf = 0; hf < NH; hf++) {
            int b = bfirst + lane + hf * 32;
            float2 pi = unpack2(acc[hf][0]);
            float2 pff = unpack2(acc[hf][1]);
            float2 pg = unpack2(acc[hf][2]);
            float2 po = unpack2(acc[hf][3]);
            float gi = pre[hf][0] + pi.x + pi.y;
            float gf = pre[hf][1] + pff.x + pff.y;
            float gg = pre[hf][2] + pg.x + pg.y;
            float go = pre[hf][3] + po.x + po.y;
            float cc = sigf(gf) * creg[hf] + sigf(gi) * tanhf(gg);
            float hh = sigf(go) * tanhf(cc);
            creg[hf] = cc;
            hout[(size_t)b * Hh + j] = hh;
            if (HASOUT)
                g_out0[((size_t)tt * Bsz + b) * (2 * Hh) + out_off + j] = hh;
        }

        grid_bar(barcnt, bargen, (unsigned)(t + 1), 128u);
    }
}

__global__ void __launch_bounds__(256) k_scan0(const float* __restrict__ w_hh) {
    const int jb = blockIdx.x, d = blockIdx.y;     // 64 x 2 = 128 CTAs
    scan_body<2, true>(jb * 8, 0, d, d * Hh,
                       w_hh + (size_t)d * G * Hh,
                       g_gx0 + (size_t)d * ((size_t)TT * Bsz * G),
                       g_h0[0][d], g_h0[1][d],
                       &g_bar[0], &g_bar[1]);
}

__global__ void __launch_bounds__(256) k_scan1(const float* __restrict__ w_hh) {
    const int jb = blockIdx.x, bh = blockIdx.y;    // 64 x 2 = 128 CTAs (batch-split)
    scan_body<1, false>(jb * 8, bh * 32, 0, 0,
                        w_hh, g_gx1f,
                        g_h1[0], g_h1[1],
                        &g_bar[2], &g_bar[3]);
}

// layer1 backward at t=T-1: first step of reverse scan from zero state -> no w_hh term
__global__ void k_l1bwd() {
    int i = blockIdx.x * 256 + threadIdx.x;   // 64*512
    int b = i >> 9, j = i & 511;
    const float* gxp = g_gx1b + b * G;
    float gi = gxp[j], gc = gxp[2 * Hh + j], go = gxp[3 * Hh + j];
    float c = sigf(gi) * tanhf(gc);           // c_old = 0
    float h = sigf(go) * tanhf(c);
    g_hb[b * Hh + j] = h;
}

// ---------------- layernorm + MLP head, one CTA per batch element ----------------
__global__ void __launch_bounds__(256) k_head(
    const float* __restrict__ ln_g, const float* __restrict__ ln_b,
    const float* __restrict__ w1,   const float* __restrict__ b1,
    const float* __restrict__ w2,   const float* __restrict__ b2,
    float* __restrict__ out)
{
    int b = blockIdx.x, tid = threadIdx.x;
    __shared__ float v[1024];
    __shared__ float red[256];
    for (int i = tid; i < Hh; i += 256) {
        v[i]      = g_h1[0][b * Hh + i];   // fwd final h: step t=511 wrote buffer (512&1)=0
        v[Hh + i] = g_hb[b * Hh + i];
    }
    __syncthreads();
    float s = 0.f;
    for (int i = tid; i < 1024; i += 256) s += v[i];
    red[tid] = s; __syncthreads();
    for (int st = 128; st > 0; st >>= 1) { if (tid < st) red[tid] += red[tid + st]; __syncthreads(); }
    float mu = red[0] * (1.0f / 1024.0f);
    __syncthreads();
    s = 0.f;
    for (int i = tid; i < 1024; i += 256) { float dd = v[i] - mu; s += dd * dd; }
    red[tid] = s; __syncthreads();
    for (int st = 128; st > 0; st >>= 1) { if (tid < st) red[tid] += red[tid + st]; __syncthreads(); }
    float rstd = rsqrtf(red[0] * (1.0f / 1024.0f) + 1e-5f);
    __syncthreads();
    for (int i = tid; i < 1024; i += 256) v[i] = (v[i] - mu) * rstd * ln_g[i] + ln_b[i];
    __syncthreads();
    float part = 0.f;
    for (int jj = tid; jj < Hh; jj += 256) {
        float acc = b1[jj];
        const float* wr = w1 + (size_t)jj * 1024;
#pragma unroll 4
        for (int k2 = 0; k2 < 1024; k2++) acc += v[k2] * wr[k2];
        part += fmaxf(acc, 0.f) * w2[jj];
    }
    red[tid] = part; __syncthreads();
    for (int st = 128; st > 0; st >>= 1) { if (tid < st) red[tid] += red[tid + st]; __syncthreads(); }
    if (tid == 0) out[b] = red[0] + b2[0];
}

// ---------------- launch ----------------
extern "C" void kernel_launch(void* const* d_in, const int* in_sizes, int n_in,
                              void* d_out, int out_size)
{
    (void)in_sizes; (void)n_in; (void)out_size;
    const float* x     = (const float*)d_in[0];
    const float* w_ih0 = (const float*)d_in[1];
    const float* w_hh0 = (const float*)d_in[2];
    const float* b_ih0 = (const float*)d_in[3];
    const float* b_hh0 = (const float*)d_in[4];
    const float* w_ih1 = (const float*)d_in[5];
    const float* w_hh1 = (const float*)d_in[6];
    const float* b_ih1 = (const float*)d_in[7];
    const float* b_hh1 = (const float*)d_in[8];
    const float* ln_g  = (const float*)d_in[9];
    const float* ln_b  = (const float*)d_in[10];
    const float* w1    = (const float*)d_in[11];
    const float* b1    = (const float*)d_in[12];
    const float* w2    = (const float*)d_in[13];
    const float* b2    = (const float*)d_in[14];
    float* out = (float*)d_out;

    const int SM0 = (16384 + 2 * 64 * 132) * 4;   // 133120 B
    const int SM1 = (16384 + 2 * 32 * 132) * 4;   //  99328 B
    cudaFuncSetAttribute(k_scan0, cudaFuncAttributeMaxDynamicSharedMemorySize, SM0);
    cudaFuncSetAttribute(k_scan1, cudaFuncAttributeMaxDynamicSharedMemorySize, SM1);

    void *p_gx0, *p_out0, *p_gx1f, *p_gx1b;
    cudaGetSymbolAddress(&p_gx0, g_gx0);
    cudaGetSymbolAddress(&p_out0, g_out0);
    cudaGetSymbolAddress(&p_gx1f, g_gx1f);
    cudaGetSymbolAddress(&p_gx1b, g_gx1b);

    k_init<<<512, 256>>>();

    // layer 0 input projections (both directions), rows m=(t,b), A remapped from x[b][t][:]
    dim3 gproj(G / 128, (Bsz * TT) / 128);
    k_sgemm_bias<<<gproj, 256>>>(x, Din, 1, w_ih0,
                                 b_ih0, b_hh0, (float*)p_gx0, Bsz * TT, G, Din);
    k_sgemm_bias<<<gproj, 256>>>(x, Din, 1, w_ih0 + (size_t)G * Din,
                                 b_ih0 + G, b_hh0 + G,
                                 (float*)p_gx0 + (size_t)TT * Bsz * G, Bsz * TT, G, Din);

    // layer 0 bidirectional scan (persistent, 128 CTAs, grid barrier per step)
    k_scan0<<<dim3(64, 2), 256, SM0>>>(w_hh0);

    // layer 1 forward projection (full) + backward projection (only t = T-1 needed)
    k_sgemm_bias<<<gproj, 256>>>((const float*)p_out0, 2 * Hh, 0, w_ih1,
                                 b_ih1, b_hh1, (float*)p_gx1f, Bsz * TT, G, 2 * Hh);
    k_sgemm_bias<<<dim3(G / 128, 1), 256>>>(
        (const float*)p_out0 + (size_t)(TT - 1) * Bsz * 2 * Hh, 2 * Hh, 0,
        w_ih1 + (size_t)G * 2 * Hh, b_ih1 + G, b_hh1 + G,
        (float*)p_gx1b, Bsz, G, 2 * Hh);

    // layer 1 forward scan (persistent, batch-split to 128 CTAs)
    k_scan1<<<dim3(64, 2), 256, SM1>>>(w_hh1);

    // layer 1 backward (single step) + head
    k_l1bwd<<<128, 256>>>();
    k_head<<<64, 256>>>(ln_g, ln_b, w1, b1, w2, b2, out);
}

// round 8
// speedup vs baseline: 1.1719x; 1.1719x over previous
#include <cuda_runtime.h>
#include <cuda_bf16.h>
#include <cstdint>
#include <math.h>

#define Bsz 64
#define TT  512
#define Din 256
#define Hh  512
#define G   2048   /* 4*H */

typedef unsigned long long ull;
typedef __nv_bfloat16 bf16;

// ---------------- scratch (static device globals; no allocation) ----------------
__device__ float g_gx0 [(size_t)2*TT*Bsz*G];    // [d][t][b][4H]
__device__ float g_out0[(size_t)TT*Bsz*2*Hh];   // [t][b][2H]
__device__ float g_gx1f[(size_t)TT*Bsz*G];      // [t][b][4H]
__device__ float g_gx1b[Bsz*G];
__device__ float g_h0[2][2][Bsz*Hh];
__device__ float g_h1[2][Bsz*Hh];
__device__ float g_hb[Bsz*Hh];
__device__ unsigned g_bar[4];

// bf16 split operands for tensor-core GEMMs
__device__ bf16 g_xhi[(size_t)TT*Bsz*Din],   g_xlo[(size_t)TT*Bsz*Din];
__device__ bf16 g_o0hi[(size_t)TT*Bsz*2*Hh], g_o0lo[(size_t)TT*Bsz*2*Hh];
__device__ bf16 g_w0hi[2*G*Din],  g_w0lo[2*G*Din];
__device__ bf16 g_w1hi[2*G*2*Hh], g_w1lo[2*G*2*Hh];

// ---------------- packed f32x2 helpers ----------------
__device__ __forceinline__ ull ffma2(ull a, ull b, ull c) {
    ull d; asm("fma.rn.f32x2 %0, %1, %2, %3;" : "=l"(d) : "l"(a), "l"(b), "l"(c)); return d;
}
__device__ __forceinline__ float2 unpack2(ull v) {
    float2 f; asm("mov.b64 {%0, %1}, %2;" : "=f"(f.x), "=f"(f.y) : "l"(v)); return f;
}
__device__ __forceinline__ float sigf(float x) { return 1.0f / (1.0f + expf(-x)); }

// ---------------- mma.sync helpers (sm_80-era, valid on base sm_100 target) -----
__device__ __forceinline__ uint32_t smem_u32(const void* p) {
    uint32_t a;
    asm("{ .reg .u64 t; cvta.to.shared.u64 t, %1; cvt.u32.u64 %0, t; }" : "=r"(a) : "l"(p));
    return a;
}
__device__ __forceinline__ void ldsm4(uint32_t* r, uint32_t addr) {
    asm volatile("ldmatrix.sync.aligned.m8n8.x4.shared.b16 {%0,%1,%2,%3}, [%4];"
                 : "=r"(r[0]), "=r"(r[1]), "=r"(r[2]), "=r"(r[3]) : "r"(addr));
}
__device__ __forceinline__ void mma16816(float* d, const uint32_t* a,
                                         uint32_t b0, uint32_t b1) {
    asm volatile(
        "mma.sync.aligned.m16n8k16.row.col.f32.bf16.bf16.f32 "
        "{%0,%1,%2,%3}, {%4,%5,%6,%7}, {%8,%9}, {%0,%1,%2,%3};"
        : "+f"(d[0]), "+f"(d[1]), "+f"(d[2]), "+f"(d[3])
        : "r"(a[0]), "r"(a[1]), "r"(a[2]), "r"(a[3]), "r"(b0), "r"(b1));
}

// ---------------- software grid barrier ----------------
__device__ __forceinline__ void grid_bar(unsigned* cnt, unsigned* gen,
                                         unsigned target, unsigned nCTA) {
    volatile unsigned* vgen = (volatile unsigned*)gen;
    __syncthreads();
    if (threadIdx.x == 0) {
        __threadfence();
        unsigned prev = atomicAdd(cnt, 1u);
        if (prev + 1u == nCTA * target) { __threadfence(); *vgen = target; }
        else { while (*vgen < target) { } }
        __threadfence();
    }
    __syncthreads();
}

__global__ void k_init() {
    int i = blockIdx.x * 256 + threadIdx.x;
    if (i < 2*2*Bsz*Hh) (&g_h0[0][0][0])[i] = 0.0f;
    if (i < 2*Bsz*Hh)   (&g_h1[0][0])[i]    = 0.0f;
    if (i < 4)          g_bar[i] = 0u;
}

// ---------------- bf16 hi/lo splitters ----------------
__global__ void k_split(const float* __restrict__ s, bf16* __restrict__ hi,
                        bf16* __restrict__ lo, int n) {
    int i = blockIdx.x * 256 + threadIdx.x;
    if (i < n) {
        float v = s[i];
        bf16 h = __float2bfloat16(v);
        hi[i] = h;
        lo[i] = __float2bfloat16(v - __bfloat162float(h));
    }
}
// x[b][t][d] -> hi/lo in [t][b][d]
__global__ void k_split_x(const float* __restrict__ x, bf16* __restrict__ hi,
                          bf16* __restrict__ lo) {
    int i = blockIdx.x * 256 + threadIdx.x;
    int d = i & (Din - 1), t = (i >> 8) & (TT - 1), b = i >> 17;
    float v = x[i];
    bf16 h = __float2bfloat16(v);
    size_t o = ((size_t)t * Bsz + b) * Din + d;
    hi[o] = h;
    lo[o] = __float2bfloat16(v - __bfloat162float(h));
}

// ---------------- HMMA bf16-split GEMM ----------------
// C[M,2048] = (Ahi+Alo)[M,K] @ ((Bhi+Blo)[2048,K])^T + bia + bib  (lo*lo dropped)
// Tile 128x128x32, 256 thr, 8 warps (2x4), warp tile 64x32, m16n8k16 fragments.
// smem: 2 stages x 4 tiles x [128][40] bf16 (stride 40 => conflict-free ldmatrix).
#define MMSM (2 * 4 * 128 * 40 * 2 + 512)

__device__ __forceinline__ uint4 g_ld4(const bf16* __restrict__ src, int K,
                                       int row, int k0, int q, int rowsv) {
    if (row < rowsv)
        return *reinterpret_cast<const uint4*>(src + (size_t)row * K + k0 + q * 8);
    return make_uint4(0u, 0u, 0u, 0u);
}

__global__ void __launch_bounds__(256) k_mma_gemm(
    const bf16* __restrict__ Ahi, const bf16* __restrict__ Alo,
    const bf16* __restrict__ Bhi, const bf16* __restrict__ Blo,
    const float* __restrict__ bia, const float* __restrict__ bib,
    float* __restrict__ C, int M, int K)
{
    extern __shared__ __align__(16) char smx[];
    bf16*  sbase = (bf16*)smx;                  // 8 tiles of 128*40 bf16
    float* bsum  = (float*)(smx + 81920);
    const int tid = threadIdx.x, wid = tid >> 5, lane = tid & 31;
    const int bn = blockIdx.x << 7, bm = blockIdx.y << 7;
    const int wm = wid >> 2, wn = wid & 3;
    const int av = (M - bm < 128) ? (M - bm) : 128;

    if (tid < 128) bsum[tid] = bia[bn + tid] + bib[bn + tid];

    const bf16* gAh = Ahi + (size_t)bm * K;
    const bf16* gAl = Alo + (size_t)bm * K;
    const bf16* gBh = Bhi + (size_t)bn * K;
    const bf16* gBl = Blo + (size_t)bn * K;

    const int r0 = tid >> 2, qq = tid & 3;       // rows r0 and r0+64, 16B chunk qq

    // preload + store stage 0
    {
        uint4 v[4][2];
        v[0][0] = g_ld4(gAh, K, r0, 0, qq, av);  v[0][1] = g_ld4(gAh, K, r0+64, 0, qq, av);
        v[1][0] = g_ld4(gAl, K, r0, 0, qq, av);  v[1][1] = g_ld4(gAl, K, r0+64, 0, qq, av);
        v[2][0] = g_ld4(gBh, K, r0, 0, qq, 128); v[2][1] = g_ld4(gBh, K, r0+64, 0, qq, 128);
        v[3][0] = g_ld4(gBl, K, r0, 0, qq, 128); v[3][1] = g_ld4(gBl, K, r0+64, 0, qq, 128);
#pragma unroll
        for (int t2 = 0; t2 < 4; t2++) {
            bf16* d = sbase + t2 * 5120;
            *reinterpret_cast<uint4*>(d + r0 * 40 + qq * 8)        = v[t2][0];
            *reinterpret_cast<uint4*>(d + (r0 + 64) * 40 + qq * 8) = v[t2][1];
        }
    }
    __syncthreads();

    float acc[4][4][4];
#pragma unroll
    for (int mi = 0; mi < 4; mi++)
#pragma unroll
        for (int ni = 0; ni < 4; ni++)
#pragma unroll
            for (int r = 0; r < 4; r++) acc[mi][ni][r] = 0.0f;

    const uint32_t sbu  = smem_u32(sbase);
    const uint32_t arow = 2u * (((uint32_t)(lane & 15)) * 40u + ((uint32_t)(lane >> 4)) * 8u);
    const int NKB = K >> 5;

    for (int kb = 0; kb < NKB; kb++) {
        uint4 v[4][2];
        const bool pf = (kb + 1 < NKB);
        if (pf) {
            const int k0 = (kb + 1) << 5;
            v[0][0] = g_ld4(gAh, K, r0, k0, qq, av);  v[0][1] = g_ld4(gAh, K, r0+64, k0, qq, av);
            v[1][0] = g_ld4(gAl, K, r0, k0, qq, av);  v[1][1] = g_ld4(gAl, K, r0+64, k0, qq, av);
            v[2][0] = g_ld4(gBh, K, r0, k0, qq, 128); v[2][1] = g_ld4(gBh, K, r0+64, k0, qq, 128);
            v[3][0] = g_ld4(gBl, K, r0, k0, qq, 128); v[3][1] = g_ld4(gBl, K, r0+64, k0, qq, 128);
        }

        const uint32_t base = sbu + ((kb & 1) ? 40960u : 0u);
        const uint32_t aA = base + arow + (uint32_t)wm * 5120u;          // A row block
        const uint32_t aB = base + 20480u + arow + (uint32_t)wn * 2560u; // B row block
#pragma unroll
        for (int kh = 0; kh < 2; kh++) {
            const uint32_t ko = (uint32_t)kh * 32u;
            uint32_t ah[4][4], al_[4][4], bh[2][4], bl_[2][4];
#pragma unroll
            for (int mi = 0; mi < 4; mi++) {
                ldsm4(ah[mi],  aA + (uint32_t)mi * 1280u + ko);
                ldsm4(al_[mi], aA + 10240u + (uint32_t)mi * 1280u + ko);
            }
#pragma unroll
            for (int nj = 0; nj < 2; nj++) {
                ldsm4(bh[nj],  aB + (uint32_t)nj * 1280u + ko);
                ldsm4(bl_[nj], aB + 10240u + (uint32_t)nj * 1280u + ko);
            }
#pragma unroll
            for (int mi = 0; mi < 4; mi++) {
#pragma unroll
                for (int ni = 0; ni < 4; ni++) {
                    const int nj = ni >> 1, sb_ = ni & 1;
                    mma16816(acc[mi][ni], ah[mi],  bh[nj][sb_], bh[nj][sb_ + 2]);
                    mma16816(acc[mi][ni], ah[mi],  bl_[nj][sb_], bl_[nj][sb_ + 2]);
                    mma16816(acc[mi][ni], al_[mi], bh[nj][sb_], bh[nj][sb_ + 2]);
                }
            }
        }

        if (pf) {
            bf16* d0 = sbase + ((kb + 1) & 1) * 20480;
#pragma unroll
            for (int t2 = 0; t2 < 4; t2++) {
                bf16* d = d0 + t2 * 5120;
                *reinterpret_cast<uint4*>(d + r0 * 40 + qq * 8)        = v[t2][0];
                *reinterpret_cast<uint4*>(d + (r0 + 64) * 40 + qq * 8) = v[t2][1];
            }
        }
        __syncthreads();
    }

    // epilogue: bias + store (float2 per fragment half-row)
#pragma unroll
    for (int mi = 0; mi < 4; mi++) {
#pragma unroll
        for (int ni = 0; ni < 4; ni++) {
            const int coll = wn * 32 + ni * 8 + (lane & 3) * 2;
            const int rowa = bm + wm * 64 + mi * 16 + (lane >> 2);
            const float bx = bsum[coll], by = bsum[coll + 1];
            if (rowa < M) {
                float2 p = make_float2(acc[mi][ni][0] + bx, acc[mi][ni][1] + by);
                *reinterpret_cast<float2*>(C + (size_t)rowa * G + bn + coll) = p;
            }
            if (rowa + 8 < M) {
                float2 p = make_float2(acc[mi][ni][2] + bx, acc[mi][ni][3] + by);
                *reinterpret_cast<float2*>(C + (size_t)(rowa + 8) * G + bn + coll) = p;
            }
        }
    }
}

// ---------------- persistent LSTM scan (unchanged from best-passing round) ------
template<int NH, bool HASOUT>
__device__ __forceinline__ void scan_body(
    int jbase, int bfirst, int rev, int out_off,
    const float* __restrict__ W,
    const float* __restrict__ gx,
    float* __restrict__ hA, float* __restrict__ hB,
    unsigned* barcnt, unsigned* bargen)
{
    constexpr int NB = 32 * NH;
    constexpr int U  = NB / 8;
    extern __shared__ float sm[];
    float* wsm = sm;
    float* hch = sm + 16384;

    const int tid  = threadIdx.x;
    const int w    = tid >> 5, lane = tid & 31;
    const int j    = jbase + w;

    for (int idx = tid; idx < 4096; idx += 256) {
        int ww = idx >> 9, gg = (idx >> 7) & 3, q = (idx & 127) << 2;
        float4 v = *reinterpret_cast<const float4*>(
            W + ((size_t)(gg * Hh + jbase + ww)) * Hh + q);
        *reinterpret_cast<float4*>(wsm + (((ww << 2) + gg) << 9) + q) = v;
    }

    float creg[NH];
#pragma unroll
    for (int hf = 0; hf < NH; hf++) creg[hf] = 0.0f;
    const float* wb_base = wsm + ((w << 2) << 9);

    for (int t = 0; t < TT; t++) {
        const int tt = rev ? (TT - 1 - t) : t;
        const float* hin  = (t & 1) ? hB : hA;
        float*       hout = (t & 1) ? hA : hB;

        float pre[NH][4];
#pragma unroll
        for (int hf = 0; hf < NH; hf++) {
            int b = bfirst + lane + hf * 32;
            const float* gp = gx + ((size_t)tt * Bsz + b) * G + j;
            pre[hf][0] = gp[0]; pre[hf][1] = gp[Hh];
            pre[hf][2] = gp[2 * Hh]; pre[hf][3] = gp[3 * Hh];
        }

        ull acc[NH][4];
#pragma unroll
        for (int hf = 0; hf < NH; hf++)
#pragma unroll
            for (int gg = 0; gg < 4; gg++) acc[hf][gg] = 0ull;

        {
            float4 pf[U];
#pragma unroll
            for (int u = 0; u < U; u++) {
                int idx = tid + u * 256;
                int r = idx >> 5, kq = (idx & 31) << 2;
                pf[u] = *reinterpret_cast<const float4*>(
                    hin + (size_t)(bfirst + r) * Hh + kq);
            }
#pragma unroll
            for (int u = 0; u < U; u++) {
                int idx = tid + u * 256;
                int r = idx >> 5, kq = (idx & 31) << 2;
                *reinterpret_cast<float4*>(hch + r * 132 + kq) = pf[u];
            }
        }
        __syncthreads();

        int buf = 0;
#pragma unroll
        for (int c = 0; c < 4; c++) {
            float4 pf[U];
            if (c < 3) {
#pragma unroll
                for (int u = 0; u < U; u++) {
                    int idx = tid + u * 256;
                    int r = idx >> 5, kq = (idx & 31) << 2;
                    pf[u] = *reinterpret_cast<const float4*>(
                        hin + (size_t)(bfirst + r) * Hh + (c + 1) * 128 + kq);
                }
            }
            const float* bp = hch + buf * (NB * 132);
            const float* wb = wb_base + c * 128;
#pragma unroll 8
            for (int kk = 0; kk < 128; kk += 4) {
                ulonglong2 wv0 = *reinterpret_cast<const ulonglong2*>(wb + 0 * 512 + kk);
                ulonglong2 wv1 = *reinterpret_cast<const ulonglong2*>(wb + 1 * 512 + kk);
                ulonglong2 wv2 = *reinterpret_cast<const ulonglong2*>(wb + 2 * 512 + kk);
                ulonglong2 wv3 = *reinterpret_cast<const ulonglong2*>(wb + 3 * 512 + kk);
#pragma unroll
                for (int hf = 0; hf < NH; hf++) {
                    ulonglong2 hv = *reinterpret_cast<const ulonglong2*>(
                        bp + (lane + hf * 32) * 132 + kk);
                    acc[hf][0] = ffma2(hv.x, wv0.x, acc[hf][0]);
                    acc[hf][1] = ffma2(hv.x, wv1.x, acc[hf][1]);
                    acc[hf][2] = ffma2(hv.x, wv2.x, acc[hf][2]);
                    acc[hf][3] = ffma2(hv.x, wv3.x, acc[hf][3]);
                    acc[hf][0] = ffma2(hv.y, wv0.y, acc[hf][0]);
                    acc[hf][1] = ffma2(hv.y, wv1.y, acc[hf][1]);
                    acc[hf][2] = ffma2(hv.y, wv2.y, acc[hf][2]);
                    acc[hf][3] = ffma2(hv.y, wv3.y, acc[hf][3]);
                }
            }
            if (c < 3) {
                float* dst = hch + (buf ^ 1) * (NB * 132);
#pragma unroll
                for (int u = 0; u < U; u++) {
                    int idx = tid + u * 256;
                    int r = idx >> 5, kq = (idx & 31) << 2;
                    *reinterpret_cast<float4*>(dst + r * 132 + kq) = pf[u];
                }
            }
            __syncthreads();
            buf ^= 1;
        }

#pragma unroll
        for (int hf = 0; hf < NH; hf++) {
            int b = bfirst + lane + hf * 32;
            float2 pi  = unpack2(acc[hf][0]);
            float2 pff = unpack2(acc[hf][1]);
            float2 pg  = unpack2(acc[hf][2]);
            float2 po  = unpack2(acc[hf][3]);
            float gi = pre[hf][0] + pi.x + pi.y;
            float gf = pre[hf][1] + pff.x + pff.y;
            float gg = pre[hf][2] + pg.x + pg.y;
            float go = pre[hf][3] + po.x + po.y;
            float cc = sigf(gf) * creg[hf] + sigf(gi) * tanhf(gg);
            float hh = sigf(go) * tanhf(cc);
            creg[hf] = cc;
            hout[(size_t)b * Hh + j] = hh;
            if (HASOUT)
                g_out0[((size_t)tt * Bsz + b) * (2 * Hh) + out_off + j] = hh;
        }
        grid_bar(barcnt, bargen, (unsigned)(t + 1), 128u);
    }
}

__global__ void __launch_bounds__(256) k_scan0(const float* __restrict__ w_hh) {
    const int jb = blockIdx.x, d = blockIdx.y;
    scan_body<2, true>(jb * 8, 0, d, d * Hh,
                       w_hh + (size_t)d * G * Hh,
                       g_gx0 + (size_t)d * ((size_t)TT * Bsz * G),
                       g_h0[0][d], g_h0[1][d], &g_bar[0], &g_bar[1]);
}
__global__ void __launch_bounds__(256) k_scan1(const float* __restrict__ w_hh) {
    const int jb = blockIdx.x, bh = blockIdx.y;
    scan_body<1, false>(jb * 8, bh * 32, 0, 0,
                        w_hh, g_gx1f, g_h1[0], g_h1[1], &g_bar[2], &g_bar[3]);
}

__global__ void k_l1bwd() {
    int i = blockIdx.x * 256 + threadIdx.x;
    int b = i >> 9, j = i & 511;
    const float* gxp = g_gx1b + b * G;
    float gi = gxp[j], gc = gxp[2 * Hh + j], go = gxp[3 * Hh + j];
    float c = sigf(gi) * tanhf(gc);
    float h = sigf(go) * tanhf(c);
    g_hb[b * Hh + j] = h;
}

__global__ void __launch_bounds__(256) k_head(
    const float* __restrict__ ln_g, const float* __restrict__ ln_b,
    const float* __restrict__ w1,   const float* __restrict__ b1,
    const float* __restrict__ w2,   const float* __restrict__ b2,
    float* __restrict__ out)
{
    int b = blockIdx.x, tid = threadIdx.x;
    __shared__ float v[1024];
    __shared__ float red[256];
    for (int i = tid; i < Hh; i += 256) {
        v[i]      = g_h1[0][b * Hh + i];
        v[Hh + i] = g_hb[b * Hh + i];
    }
    __syncthreads();
    float s = 0.f;
    for (int i = tid; i < 1024; i += 256) s += v[i];
    red[tid] = s; __syncthreads();
    for (int st = 128; st > 0; st >>= 1) { if (tid < st) red[tid] += red[tid + st]; __syncthreads(); }
    float mu = red[0] * (1.0f / 1024.0f);
    __syncthreads();
    s = 0.f;
    for (int i = tid; i < 1024; i += 256) { float dd = v[i] - mu; s += dd * dd; }
    red[tid] = s; __syncthreads();
    for (int st = 128; st > 0; st >>= 1) { if (tid < st) red[tid] += red[tid + st]; __syncthreads(); }
    float rstd = rsqrtf(red[0] * (1.0f / 1024.0f) + 1e-5f);
    __syncthreads();
    for (int i = tid; i < 1024; i += 256) v[i] = (v[i] - mu) * rstd * ln_g[i] + ln_b[i];
    __syncthreads();
    float part = 0.f;
    for (int jj = tid; jj < Hh; jj += 256) {
        float acc = b1[jj];
        const float* wr = w1 + (size_t)jj * 1024;
#pragma unroll 4
        for (int k2 = 0; k2 < 1024; k2++) acc += v[k2] * wr[k2];
        part += fmaxf(acc, 0.f) * w2[jj];
    }
    red[tid] = part; __syncthreads();
    for (int st = 128; st > 0; st >>= 1) { if (tid < st) red[tid] += red[tid + st]; __syncthreads(); }
    if (tid == 0) out[b] = red[0] + b2[0];
}

// ---------------- launch ----------------
extern "C" void kernel_launch(void* const* d_in, const int* in_sizes, int n_in,
                              void* d_out, int out_size)
{
    (void)in_sizes; (void)n_in; (void)out_size;
    const float* x     = (const float*)d_in[0];
    const float* w_ih0 = (const float*)d_in[1];
    const float* w_hh0 = (const float*)d_in[2];
    const float* b_ih0 = (const float*)d_in[3];
    const float* b_hh0 = (const float*)d_in[4];
    const float* w_ih1 = (const float*)d_in[5];
    const float* w_hh1 = (const float*)d_in[6];
    const float* b_ih1 = (const float*)d_in[7];
    const float* b_hh1 = (const float*)d_in[8];
    const float* ln_g  = (const float*)d_in[9];
    const float* ln_b  = (const float*)d_in[10];
    const float* w1    = (const float*)d_in[11];
    const float* b1    = (const float*)d_in[12];
    const float* w2    = (const float*)d_in[13];
    const float* b2    = (const float*)d_in[14];
    float* out = (float*)d_out;

    const int SM0 = (16384 + 2 * 64 * 132) * 4;
    const int SM1 = (16384 + 2 * 32 * 132) * 4;
    cudaFuncSetAttribute(k_scan0, cudaFuncAttributeMaxDynamicSharedMemorySize, SM0);
    cudaFuncSetAttribute(k_scan1, cudaFuncAttributeMaxDynamicSharedMemorySize, SM1);
    cudaFuncSetAttribute(k_mma_gemm, cudaFuncAttributeMaxDynamicSharedMemorySize, MMSM);

    void *p_gx0, *p_out0, *p_gx1f, *p_gx1b;
    void *p_xhi, *p_xlo, *p_o0hi, *p_o0lo, *p_w0hi, *p_w0lo, *p_w1hi, *p_w1lo;
    cudaGetSymbolAddress(&p_gx0, g_gx0);
    cudaGetSymbolAddress(&p_out0, g_out0);
    cudaGetSymbolAddress(&p_gx1f, g_gx1f);
    cudaGetSymbolAddress(&p_gx1b, g_gx1b);
    cudaGetSymbolAddress(&p_xhi, g_xhi);   cudaGetSymbolAddress(&p_xlo, g_xlo);
    cudaGetSymbolAddress(&p_o0hi, g_o0hi); cudaGetSymbolAddress(&p_o0lo, g_o0lo);
    cudaGetSymbolAddress(&p_w0hi, g_w0hi); cudaGetSymbolAddress(&p_w0lo, g_w0lo);
    cudaGetSymbolAddress(&p_w1hi, g_w1hi); cudaGetSymbolAddress(&p_w1lo, g_w1lo);

    k_init<<<512, 256>>>();

    // splits for layer 0
    k_split_x<<<(TT * Bsz * Din) / 256, 256>>>(x, (bf16*)p_xhi, (bf16*)p_xlo);
    k_split<<<(2 * G * Din) / 256, 256>>>(w_ih0, (bf16*)p_w0hi, (bf16*)p_w0lo, 2 * G * Din);

    // layer 0 input projections (HMMA), rows m=(t,b)
    dim3 gg(16, 256);
    k_mma_gemm<<<gg, 256, MMSM>>>((bf16*)p_xhi, (bf16*)p_xlo,
                                  (bf16*)p_w0hi, (bf16*)p_w0lo,
                                  b_ih0, b_hh0, (float*)p_gx0, Bsz * TT, Din);
    k_mma_gemm<<<gg, 256, MMSM>>>((bf16*)p_xhi, (bf16*)p_xlo,
                                  (bf16*)p_w0hi + (size_t)G * Din, (bf16*)p_w0lo + (size_t)G * Din,
                                  b_ih0 + G, b_hh0 + G,
                                  (float*)p_gx0 + (size_t)TT * Bsz * G, Bsz * TT, Din);

    // layer 0 bidirectional scan
    k_scan0<<<dim3(64, 2), 256, SM0>>>(w_hh0);

    // splits for layer 1
    k_split<<<(TT * Bsz * 2 * Hh) / 256, 256>>>((const float*)p_out0,
                                                (bf16*)p_o0hi, (bf16*)p_o0lo, TT * Bsz * 2 * Hh);
    k_split<<<(2 * G * 2 * Hh) / 256, 256>>>(w_ih1, (bf16*)p_w1hi, (bf16*)p_w1lo, 2 * G * 2 * Hh);

    // layer 1 fwd projection (full) + bwd projection (only t = T-1)
    k_mma_gemm<<<gg, 256, MMSM>>>((bf16*)p_o0hi, (bf16*)p_o0lo,
                                  (bf16*)p_w1hi, (bf16*)p_w1lo,
                                  b_ih1, b_hh1, (float*)p_gx1f, Bsz * TT, 2 * Hh);
    k_mma_gemm<<<dim3(16, 1), 256, MMSM>>>(
        (bf16*)p_o0hi + (size_t)(TT - 1) * Bsz * 2 * Hh,
        (bf16*)p_o0lo + (size_t)(TT - 1) * Bsz * 2 * Hh,
        (bf16*)p_w1hi + (size_t)G * 2 * Hh, (bf16*)p_w1lo + (size_t)G * 2 * Hh,
        b_ih1 + G, b_hh1 + G, (float*)p_gx1b, Bsz, 2 * Hh);

    // layer 1 forward scan
    k_scan1<<<dim3(64, 2), 256, SM1>>>(w_hh1);

    k_l1bwd<<<128, 256>>>();
    k_head<<<64, 256>>>(ln_g, ln_b, w1, b1, w2, b2, out);
}

// round 9
// speedup vs baseline: 2.0968x; 1.7893x over previous
#include <cuda_runtime.h>
#include <cuda_bf16.h>
#include <cstdint>
#include <math.h>

#define Bsz 64
#define TT  512
#define Din 256
#define Hh  512
#define G   2048   /* 4*H */

typedef unsigned long long ull;
typedef __nv_bfloat16 bf16;

// ---------------- scratch (static device globals; no allocation) ----------------
__device__ float g_gx0 [(size_t)2*TT*Bsz*G];    // [d][t][b][4H]
__device__ float g_gx1f[(size_t)TT*Bsz*G];      // [t][b][4H]
__device__ float g_gx1b[Bsz*G];
__device__ float g_h1f[Bsz*Hh];                 // layer1 fwd linear h (final used)
__device__ float g_hb[Bsz*Hh];                  // layer1 bwd one-step hidden
__device__ unsigned g_bar[4];

// bf16 split operands for projection GEMMs
__device__ bf16 g_xhi[(size_t)TT*Bsz*Din],   g_xlo[(size_t)TT*Bsz*Din];
__device__ bf16 g_o0hi[(size_t)TT*Bsz*2*Hh], g_o0lo[(size_t)TT*Bsz*2*Hh];
__device__ bf16 g_w0hi[2*G*Din],  g_w0lo[2*G*Din];
__device__ bf16 g_w1hi[2*G*2*Hh], g_w1lo[2*G*2*Hh];

// h state in MMA A-fragment layout: [kt(32)][mt(4)][lane(32)][reg 0-3 hi, 4-7 lo]
__device__ uint32_t g_f0[2][2][32768];          // [dir][pingpong]
__device__ uint32_t g_f1[2][32768];             // layer1 fwd [pingpong]
// W_hh in MMA B-fragment layout, per CTA slice
__device__ uint32_t g_wf0[2*64*16384];          // [dir][cta64]: [kt32][nt4][lane32][b0h,b1h,b0l,b1l]
__device__ uint32_t g_wf1[128*8192];            // [cta128]:    [kt32][nt2][lane32][4]

__device__ __forceinline__ float sigf(float x) { return 1.0f / (1.0f + expf(-x)); }

// ---------------- mma.sync helpers (sm_80-era, valid on base sm_100 target) -----
__device__ __forceinline__ uint32_t smem_u32(const void* p) {
    uint32_t a;
    asm("{ .reg .u64 t; cvta.to.shared.u64 t, %1; cvt.u32.u64 %0, t; }" : "=r"(a) : "l"(p));
    return a;
}
__device__ __forceinline__ void ldsm4(uint32_t* r, uint32_t addr) {
    asm volatile("ldmatrix.sync.aligned.m8n8.x4.shared.b16 {%0,%1,%2,%3}, [%4];"
                 : "=r"(r[0]), "=r"(r[1]), "=r"(r[2]), "=r"(r[3]) : "r"(addr));
}
__device__ __forceinline__ void mma16816(float* d, const uint32_t* a,
                                         uint32_t b0, uint32_t b1) {
    asm volatile(
        "mma.sync.aligned.m16n8k16.row.col.f32.bf16.bf16.f32 "
        "{%0,%1,%2,%3}, {%4,%5,%6,%7}, {%8,%9}, {%0,%1,%2,%3};"
        : "+f"(d[0]), "+f"(d[1]), "+f"(d[2]), "+f"(d[3])
        : "r"(a[0]), "r"(a[1]), "r"(a[2]), "r"(a[3]), "r"(b0), "r"(b1));
}

// ---------------- software grid barrier ----------------
__device__ __forceinline__ void grid_bar(unsigned* cnt, unsigned* gen,
                                         unsigned target, unsigned nCTA) {
    volatile unsigned* vgen = (volatile unsigned*)gen;
    __syncthreads();
    if (threadIdx.x == 0) {
        __threadfence();
        unsigned prev = atomicAdd(cnt, 1u);
        if (prev + 1u == nCTA * target) { __threadfence(); *vgen = target; }
        else { while (*vgen < target) { } }
        __threadfence();
    }
    __syncthreads();
}

__global__ void k_init() {
    int i = blockIdx.x * 256 + threadIdx.x;     // 512 blocks -> i < 131072
    if (i < 131072) (&g_f0[0][0][0])[i] = 0u;
    if (i < 65536)  (&g_f1[0][0])[i]    = 0u;
    if (i < 4)      g_bar[i] = 0u;
}

// ---------------- bf16 hi/lo splitters ----------------
__global__ void k_split(const float* __restrict__ s, bf16* __restrict__ hi,
                        bf16* __restrict__ lo, int n) {
    int i = blockIdx.x * 256 + threadIdx.x;
    if (i < n) {
        float v = s[i];
        bf16 h = __float2bfloat16(v);
        hi[i] = h;
        lo[i] = __float2bfloat16(v - __bfloat162float(h));
    }
}
// x[b][t][d] -> hi/lo in [t][b][d]
__global__ void k_split_x(const float* __restrict__ x, bf16* __restrict__ hi,
                          bf16* __restrict__ lo) {
    int i = blockIdx.x * 256 + threadIdx.x;
    int d = i & (Din - 1), t = (i >> 8) & (TT - 1), b = i >> 17;
    float v = x[i];
    bf16 h = __float2bfloat16(v);
    size_t o = ((size_t)t * Bsz + b) * Din + d;
    hi[o] = h;
    lo[o] = __float2bfloat16(v - __bfloat162float(h));
}

// ---------------- W_hh -> B-fragment precompute ----------------
// B frag m16n8k16: element (n,k): lane=(n&7)*4+((k&7)>>1), b0 if (k&15)<8 else b1, pos=k&1.
__device__ __forceinline__ void wfrag_pack(float wx, float wy, uint32_t& whi, uint32_t& wlo) {
    bf16 h0 = __float2bfloat16(wx), h1 = __float2bfloat16(wy);
    bf16 l0 = __float2bfloat16(wx - __bfloat162float(h0));
    bf16 l1 = __float2bfloat16(wy - __bfloat162float(h1));
    whi = (uint32_t)__bfloat16_as_ushort(h0) | ((uint32_t)__bfloat16_as_ushort(h1) << 16);
    wlo = (uint32_t)__bfloat16_as_ushort(l0) | ((uint32_t)__bfloat16_as_ushort(l1) << 16);
}

__global__ void k_wfrag0(const float* __restrict__ w) {   // w_hh0 [2][2048][512]
    int idx = blockIdx.x * 256 + threadIdx.x;             // 4096 blocks -> < 1048576
    int d  = idx >> 19;
    int r  = (idx >> 8) & 2047;
    int k  = (idx & 255) * 2;
    int gg = r >> 9, jj = r & 511;
    int cta = jj >> 3, u = jj & 7;
    int ngl = gg * 8 + u, nt = ngl >> 3, nc = ngl & 7;
    int kt = k >> 4;
    int lane2 = (nc << 2) | ((k & 7) >> 1);
    int reg = ((k & 15) >= 8) ? 1 : 0;
    float2 wv = *(const float2*)(w + ((size_t)d * G + r) * Hh + k);
    uint32_t whi, wlo; wfrag_pack(wv.x, wv.y, whi, wlo);
    size_t base = ((size_t)d * 64 + cta) * 16384 + ((size_t)(kt * 4 + nt) * 32 + lane2) * 4;
    g_wf0[base + reg]     = whi;
    g_wf0[base + reg + 2] = wlo;
}

__global__ void k_wfrag1(const float* __restrict__ w) {   // w_hh1 dir0 [2048][512]
    int idx = blockIdx.x * 256 + threadIdx.x;             // 2048 blocks -> < 524288
    int r  = idx >> 8;
    int k  = (idx & 255) * 2;
    int gg = r >> 9, jj = r & 511;
    int cta = jj >> 2, u = jj & 3;
    int ngl = gg * 4 + u, nt = ngl >> 3, nc = ngl & 7;
    int kt = k >> 4;
    int lane2 = (nc << 2) | ((k & 7) >> 1);
    int reg = ((k & 15) >= 8) ? 1 : 0;
    float2 wv = *(const float2*)(w + (size_t)r * Hh + k);
    uint32_t whi, wlo; wfrag_pack(wv.x, wv.y, whi, wlo);
    size_t base = (size_t)cta * 8192 + ((size_t)(kt * 2 + nt) * 32 + lane2) * 4;
    g_wf1[base + reg]     = whi;
    g_wf1[base + reg + 2] = wlo;
}

// ---------------- HMMA bf16-split projection GEMM (unchanged, proven) -----------
#define MMSM (2 * 4 * 128 * 40 * 2 + 512)

__device__ __forceinline__ uint4 g_ld4(const bf16* __restrict__ src, int K,
                                       int row, int k0, int q, int rowsv) {
    if (row < rowsv)
        return *reinterpret_cast<const uint4*>(src + (size_t)row * K + k0 + q * 8);
    return make_uint4(0u, 0u, 0u, 0u);
}

__global__ void __launch_bounds__(256) k_mma_gemm(
    const bf16* __restrict__ Ahi, const bf16* __restrict__ Alo,
    const bf16* __restrict__ Bhi, const bf16* __restrict__ Blo,
    const float* __restrict__ bia, const float* __restrict__ bib,
    float* __restrict__ C, int M, int K)
{
    extern __shared__ __align__(16) char smx[];
    bf16*  sbase = (bf16*)smx;
    float* bsum  = (float*)(smx + 81920);
    const int tid = threadIdx.x, wid = tid >> 5, lane = tid & 31;
    const int bn = blockIdx.x << 7, bm = blockIdx.y << 7;
    const int wm = wid >> 2, wn = wid & 3;
    const int av = (M - bm < 128) ? (M - bm) : 128;

    if (tid < 128) bsum[tid] = bia[bn + tid] + bib[bn + tid];

    const bf16* gAh = Ahi + (size_t)bm * K;
    const bf16* gAl = Alo + (size_t)bm * K;
    const bf16* gBh = Bhi + (size_t)bn * K;
    const bf16* gBl = Blo + (size_t)bn * K;

    const int r0 = tid >> 2, qq = tid & 3;

    {
        uint4 v[4][2];
        v[0][0] = g_ld4(gAh, K, r0, 0, qq, av);  v[0][1] = g_ld4(gAh, K, r0+64, 0, qq, av);
        v[1][0] = g_ld4(gAl, K, r0, 0, qq, av);  v[1][1] = g_ld4(gAl, K, r0+64, 0, qq, av);
        v[2][0] = g_ld4(gBh, K, r0, 0, qq, 128); v[2][1] = g_ld4(gBh, K, r0+64, 0, qq, 128);
        v[3][0] = g_ld4(gBl, K, r0, 0, qq, 128); v[3][1] = g_ld4(gBl, K, r0+64, 0, qq, 128);
#pragma unroll
        for (int t2 = 0; t2 < 4; t2++) {
            bf16* d = sbase + t2 * 5120;
            *reinterpret_cast<uint4*>(d + r0 * 40 + qq * 8)        = v[t2][0];
            *reinterpret_cast<uint4*>(d + (r0 + 64) * 40 + qq * 8) = v[t2][1];
        }
    }
    __syncthreads();

    float acc[4][4][4];
#pragma unroll
    for (int mi = 0; mi < 4; mi++)
#pragma unroll
        for (int ni = 0; ni < 4; ni++)
#pragma unroll
            for (int r = 0; r < 4; r++) acc[mi][ni][r] = 0.0f;

    const uint32_t sbu  = smem_u32(sbase);
    const uint32_t arow = 2u * (((uint32_t)(lane & 15)) * 40u + ((uint32_t)(lane >> 4)) * 8u);
    const int NKB = K >> 5;

    for (int kb = 0; kb < NKB; kb++) {
        uint4 v[4][2];
        const bool pf = (kb + 1 < NKB);
        if (pf) {
            const int k0 = (kb + 1) << 5;
            v[0][0] = g_ld4(gAh, K, r0, k0, qq, av);  v[0][1] = g_ld4(gAh, K, r0+64, k0, qq, av);
            v[1][0] = g_ld4(gAl, K, r0, k0, qq, av);  v[1][1] = g_ld4(gAl, K, r0+64, k0, qq, av);
            v[2][0] = g_ld4(gBh, K, r0, k0, qq, 128); v[2][1] = g_ld4(gBh, K, r0+64, k0, qq, 128);
            v[3][0] = g_ld4(gBl, K, r0, k0, qq, 128); v[3][1] = g_ld4(gBl, K, r0+64, k0, qq, 128);
        }

        const uint32_t base = sbu + ((kb & 1) ? 40960u : 0u);
        const uint32_t aA = base + arow + (uint32_t)wm * 5120u;
        const uint32_t aB = base + 20480u + arow + (uint32_t)wn * 2560u;
#pragma unroll
        for (int kh = 0; kh < 2; kh++) {
            const uint32_t ko = (uint32_t)kh * 32u;
            uint32_t ah[4][4], al_[4][4], bh[2][4], bl_[2][4];
#pragma unroll
            for (int mi = 0; mi < 4; mi++) {
                ldsm4(ah[mi],  aA + (uint32_t)mi * 1280u + ko);
                ldsm4(al_[mi], aA + 10240u + (uint32_t)mi * 1280u + ko);
            }
#pragma unroll
            for (int nj = 0; nj < 2; nj++) {
                ldsm4(bh[nj],  aB + (uint32_t)nj * 1280u + ko);
                ldsm4(bl_[nj], aB + 10240u + (uint32_t)nj * 1280u + ko);
            }
#pragma unroll
            for (int mi = 0; mi < 4; mi++) {
#pragma unroll
                for (int ni = 0; ni < 4; ni++) {
                    const int nj = ni >> 1, sb_ = ni & 1;
                    mma16816(acc[mi][ni], ah[mi],  bh[nj][sb_], bh[nj][sb_ + 2]);
                    mma16816(acc[mi][ni], ah[mi],  bl_[nj][sb_], bl_[nj][sb_ + 2]);
                    mma16816(acc[mi][ni], al_[mi], bh[nj][sb_], bh[nj][sb_ + 2]);
                }
            }
        }

        if (pf) {
            bf16* d0 = sbase + ((kb + 1) & 1) * 20480;
#pragma unroll
            for (int t2 = 0; t2 < 4; t2++) {
                bf16* d = d0 + t2 * 5120;
                *reinterpret_cast<uint4*>(d + r0 * 40 + qq * 8)        = v[t2][0];
                *reinterpret_cast<uint4*>(d + (r0 + 64) * 40 + qq * 8) = v[t2][1];
            }
        }
        __syncthreads();
    }

#pragma unroll
    for (int mi = 0; mi < 4; mi++) {
#pragma unroll
        for (int ni = 0; ni < 4; ni++) {
            const int coll = wn * 32 + ni * 8 + (lane & 3) * 2;
            const int rowa = bm + wm * 64 + mi * 16 + (lane >> 2);
            const float bx = bsum[coll], by = bsum[coll + 1];
            if (rowa < M) {
                float2 p = make_float2(acc[mi][ni][0] + bx, acc[mi][ni][1] + by);
                *reinterpret_cast<float2*>(C + (size_t)rowa * G + bn + coll) = p;
            }
            if (rowa + 8 < M) {
                float2 p = make_float2(acc[mi][ni][2] + bx, acc[mi][ni][3] + by);
                *reinterpret_cast<float2*>(C + (size_t)(rowa + 8) * G + bn + coll) = p;
            }
        }
    }
}

// ---------------- persistent tensor-core LSTM scan ----------------
// CTA owns NU hidden units (N = 4*NU gate cols), all 64 batches. Per step:
// gates[64,N] = h[64,512] @ Wslice^T via m16n8k16 bf16-split (3 terms), K-split-4
// across warp groups, partials combined in smem. h passed between steps in global
// A-fragment layout (hi/lo packed words) -> next step loads fragments directly.
template<int NU, bool L0>
__global__ void __launch_bounds__(256, 1) k_scan_mma() {
    constexpr int NT = NU / 2;        // B n-tiles (8 cols each)
    constexpr int N  = NU * 4;
    constexpr int NP = N + 2;
    __shared__ float gd[4][64][NP];
    __shared__ float c_sm[64][NU];

    const int tid = threadIdx.x, wid = tid >> 5, lane = tid & 31;
    const int kh = wid >> 1, mh = wid & 1;
    const int tig = lane & 3, gid = lane >> 2;

    const int cta = blockIdx.x;
    const int dir = L0 ? blockIdx.y : 0;
    const int rev = L0 ? dir : 0;
    const int jbase = cta * NU;

    const float* gx = L0 ? (g_gx0 + (size_t)dir * TT * Bsz * G) : g_gx1f;
    const uint4* wf = L0 ? (const uint4*)(g_wf0 + ((size_t)dir * 64 + cta) * 16384)
                         : (const uint4*)(g_wf1 + (size_t)cta * 8192);
    uint32_t* f0 = L0 ? g_f0[dir][0] : g_f1[0];
    uint32_t* f1 = L0 ? g_f0[dir][1] : g_f1[1];
    unsigned* bc = L0 ? &g_bar[0] : &g_bar[2];
    unsigned* bg = L0 ? &g_bar[1] : &g_bar[3];

    for (int i = tid; i < 64 * NU; i += 256) ((float*)c_sm)[i] = 0.f;

    // pointwise role: thread -> (batch pb, unit-pair ppi)
    constexpr int PSH = (NU == 8) ? 2 : 1;
    const int pb  = tid >> PSH;
    const int ppi = tid & ((1 << PSH) - 1);
    const bool pact = (NU == 8) || (tid < 128);
    const int jg = jbase + 2 * ppi;
    // A-fragment address for h element pair (pb, jg..jg+1)
    const int fc = jg & 15, fr = pb & 15, fmt = pb >> 4, fkt = jg >> 4;
    const int flane = ((fr & 7) << 2) | ((fc & 7) >> 1);
    const int freg  = ((fr >> 3) & 1) | (((fc >> 3) & 1) << 1);
    const int faddr = ((fkt * 4 + fmt) * 32 + flane) * 8 + freg;

    __syncthreads();

    for (int t = 0; t < TT; t++) {
        const int tt = rev ? (TT - 1 - t) : t;
        const uint32_t* fin = (t & 1) ? f1 : f0;
        uint32_t* fout = (t & 1) ? f0 : f1;

        // prefetch gate pre-activations (independent of h)
        float2 pre[4];
        if (pact) {
            const float* gp = gx + ((size_t)tt * Bsz + pb) * G + jg;
            pre[0] = __ldcs((const float2*)gp);
            pre[1] = __ldcs((const float2*)(gp + 512));
            pre[2] = __ldcs((const float2*)(gp + 1024));
            pre[3] = __ldcs((const float2*)(gp + 1536));
        }

        float acc[2][NT][4];
#pragma unroll
        for (int m2 = 0; m2 < 2; m2++)
#pragma unroll
            for (int nt = 0; nt < NT; nt++)
#pragma unroll
                for (int r = 0; r < 4; r++) acc[m2][nt][r] = 0.f;

        for (int k8 = 0; k8 < 8; k8++) {
            const int kt = kh * 8 + k8;
            uint4 Ah[2], Al[2], Bv[NT];
#pragma unroll
            for (int m2 = 0; m2 < 2; m2++) {
                const uint32_t* ap = fin + ((size_t)(kt * 4 + mh * 2 + m2) * 32 + lane) * 8;
                Ah[m2] = __ldcg((const uint4*)ap);
                Al[m2] = __ldcg((const uint4*)(ap + 4));
            }
#pragma unroll
            for (int nt = 0; nt < NT; nt++)
                Bv[nt] = __ldg(wf + (size_t)(kt * NT + nt) * 32 + lane);
#pragma unroll
            for (int m2 = 0; m2 < 2; m2++) {
                uint32_t ah[4] = {Ah[m2].x, Ah[m2].y, Ah[m2].z, Ah[m2].w};
                uint32_t al[4] = {Al[m2].x, Al[m2].y, Al[m2].z, Al[m2].w};
#pragma unroll
                for (int nt = 0; nt < NT; nt++) {
                    mma16816(acc[m2][nt], ah, Bv[nt].x, Bv[nt].y);   // hi*hi
                    mma16816(acc[m2][nt], ah, Bv[nt].z, Bv[nt].w);   // hi*lo
                    mma16816(acc[m2][nt], al, Bv[nt].x, Bv[nt].y);   // lo*hi
                }
            }
        }

        // dump partials (per k-quarter) to smem
#pragma unroll
        for (int m2 = 0; m2 < 2; m2++) {
            const int rb = (mh * 2 + m2) * 16 + gid;
#pragma unroll
            for (int nt = 0; nt < NT; nt++) {
                const int col = nt * 8 + tig * 2;
                *(float2*)&gd[kh][rb][col]     = make_float2(acc[m2][nt][0], acc[m2][nt][1]);
                *(float2*)&gd[kh][rb + 8][col] = make_float2(acc[m2][nt][2], acc[m2][nt][3]);
            }
        }
        __syncthreads();

        if (pact) {
            float hv[2];
#pragma unroll
            for (int uu = 0; uu < 2; uu++) {
                const int u = 2 * ppi + uu;
                float gi = uu ? pre[0].y : pre[0].x;
                float gf = uu ? pre[1].y : pre[1].x;
                float gc = uu ? pre[2].y : pre[2].x;
                float go = uu ? pre[3].y : pre[3].x;
#pragma unroll
                for (int q = 0; q < 4; q++) {
                    gi += gd[q][pb][0 * NU + u];
                    gf += gd[q][pb][1 * NU + u];
                    gc += gd[q][pb][2 * NU + u];
                    go += gd[q][pb][3 * NU + u];
                }
                float cc = sigf(gf) * c_sm[pb][u] + sigf(gi) * tanhf(gc);
                float hh = sigf(go) * tanhf(cc);
                c_sm[pb][u] = cc;
                hv[uu] = hh;
            }
            bf16 h0h = __float2bfloat16(hv[0]);
            bf16 h1h = __float2bfloat16(hv[1]);
            bf16 h0l = __float2bfloat16(hv[0] - __bfloat162float(h0h));
            bf16 h1l = __float2bfloat16(hv[1] - __bfloat162float(h1h));
            uint32_t whi = (uint32_t)__bfloat16_as_ushort(h0h) | ((uint32_t)__bfloat16_as_ushort(h1h) << 16);
            uint32_t wlo = (uint32_t)__bfloat16_as_ushort(h0l) | ((uint32_t)__bfloat16_as_ushort(h1l) << 16);
            __stcg((unsigned int*)&fout[faddr], whi);
            __stcg((unsigned int*)&fout[faddr + 4], wlo);
            if (L0) {
                const size_t oo = ((size_t)tt * Bsz + pb) * (2 * Hh) + (size_t)dir * Hh + jg;
                __stcg((unsigned int*)&g_o0hi[oo], whi);
                __stcg((unsigned int*)&g_o0lo[oo], wlo);
            } else {
                g_h1f[(size_t)pb * Hh + jg]     = hv[0];
                g_h1f[(size_t)pb * Hh + jg + 1] = hv[1];
            }
        }
        grid_bar(bc, bg, (unsigned)(t + 1), 128u);
    }
}

// layer1 backward at t=T-1: first step of reverse scan from zero state
__global__ void k_l1bwd() {
    int i = blockIdx.x * 256 + threadIdx.x;
    int b = i >> 9, j = i & 511;
    const float* gxp = g_gx1b + b * G;
    float gi = gxp[j], gc = gxp[2 * Hh + j], go = gxp[3 * Hh + j];
    float c = sigf(gi) * tanhf(gc);
    float h = sigf(go) * tanhf(c);
    g_hb[b * Hh + j] = h;
}

// ---------------- layernorm + MLP head ----------------
__global__ void __launch_bounds__(256) k_head(
    const float* __restrict__ ln_g, const float* __restrict__ ln_b,
    const float* __restrict__ w1,   const float* __restrict__ b1,
    const float* __restrict__ w2,   const float* __restrict__ b2,
    float* __restrict__ out)
{
    int b = blockIdx.x, tid = threadIdx.x;
    __shared__ float v[1024];
    __shared__ float red[256];
    for (int i = tid; i < Hh; i += 256) {
        v[i]      = g_h1f[b * Hh + i];
        v[Hh + i] = g_hb[b * Hh + i];
    }
    __syncthreads();
    float s = 0.f;
    for (int i = tid; i < 1024; i += 256) s += v[i];
    red[tid] = s; __syncthreads();
    for (int st = 128; st > 0; st >>= 1) { if (tid < st) red[tid] += red[tid + st]; __syncthreads(); }
    float mu = red[0] * (1.0f / 1024.0f);
    __syncthreads();
    s = 0.f;
    for (int i = tid; i < 1024; i += 256) { float dd = v[i] - mu; s += dd * dd; }
    red[tid] = s; __syncthreads();
    for (int st = 128; st > 0; st >>= 1) { if (tid < st) red[tid] += red[tid + st]; __syncthreads(); }
    float rstd = rsqrtf(red[0] * (1.0f / 1024.0f) + 1e-5f);
    __syncthreads();
    for (int i = tid; i < 1024; i += 256) v[i] = (v[i] - mu) * rstd * ln_g[i] + ln_b[i];
    __syncthreads();
    float part = 0.f;
    for (int jj = tid; jj < Hh; jj += 256) {
        float acc = b1[jj];
        const float* wr = w1 + (size_t)jj * 1024;
#pragma unroll 4
        for (int k2 = 0; k2 < 1024; k2++) acc += v[k2] * wr[k2];
        part += fmaxf(acc, 0.f) * w2[jj];
    }
    red[tid] = part; __syncthreads();
    for (int st = 128; st > 0; st >>= 1) { if (tid < st) red[tid] += red[tid + st]; __syncthreads(); }
    if (tid == 0) out[b] = red[0] + b2[0];
}

// ---------------- launch ----------------
extern "C" void kernel_launch(void* const* d_in, const int* in_sizes, int n_in,
                              void* d_out, int out_size)
{
    (void)in_sizes; (void)n_in; (void)out_size;
    const float* x     = (const float*)d_in[0];
    const float* w_ih0 = (const float*)d_in[1];
    const float* w_hh0 = (const float*)d_in[2];
    const float* b_ih0 = (const float*)d_in[3];
    const float* b_hh0 = (const float*)d_in[4];
    const float* w_ih1 = (const float*)d_in[5];
    const float* w_hh1 = (const float*)d_in[6];
    const float* b_ih1 = (const float*)d_in[7];
    const float* b_hh1 = (const float*)d_in[8];
    const float* ln_g  = (const float*)d_in[9];
    const float* ln_b  = (const float*)d_in[10];
    const float* w1    = (const float*)d_in[11];
    const float* b1    = (const float*)d_in[12];
    const float* w2    = (const float*)d_in[13];
    const float* b2    = (const float*)d_in[14];
    float* out = (float*)d_out;

    cudaFuncSetAttribute(k_mma_gemm, cudaFuncAttributeMaxDynamicSharedMemorySize, MMSM);

    void *p_gx0, *p_gx1f, *p_gx1b;
    void *p_xhi, *p_xlo, *p_o0hi, *p_o0lo, *p_w0hi, *p_w0lo, *p_w1hi, *p_w1lo;
    cudaGetSymbolAddress(&p_gx0, g_gx0);
    cudaGetSymbolAddress(&p_gx1f, g_gx1f);
    cudaGetSymbolAddress(&p_gx1b, g_gx1b);
    cudaGetSymbolAddress(&p_xhi, g_xhi);   cudaGetSymbolAddress(&p_xlo, g_xlo);
    cudaGetSymbolAddress(&p_o0hi, g_o0hi); cudaGetSymbolAddress(&p_o0lo, g_o0lo);
    cudaGetSymbolAddress(&p_w0hi, g_w0hi); cudaGetSymbolAddress(&p_w0lo, g_w0lo);
    cudaGetSymbolAddress(&p_w1hi, g_w1hi); cudaGetSymbolAddress(&p_w1lo, g_w1lo);

    k_init<<<512, 256>>>();

    // operand prep
    k_split_x<<<(TT * Bsz * Din) / 256, 256>>>(x, (bf16*)p_xhi, (bf16*)p_xlo);
    k_split<<<(2 * G * Din) / 256, 256>>>(w_ih0, (bf16*)p_w0hi, (bf16*)p_w0lo, 2 * G * Din);
    k_wfrag0<<<4096, 256>>>(w_hh0);
    k_wfrag1<<<2048, 256>>>(w_hh1);
    k_split<<<(2 * G * 2 * Hh) / 256, 256>>>(w_ih1, (bf16*)p_w1hi, (bf16*)p_w1lo, 2 * G * 2 * Hh);

    // layer 0 input projections, rows m=(t,b)
    dim3 gg(16, 256);
    k_mma_gemm<<<gg, 256, MMSM>>>((bf16*)p_xhi, (bf16*)p_xlo,
                                  (bf16*)p_w0hi, (bf16*)p_w0lo,
                                  b_ih0, b_hh0, (float*)p_gx0, Bsz * TT, Din);
    k_mma_gemm<<<gg, 256, MMSM>>>((bf16*)p_xhi, (bf16*)p_xlo,
                                  (bf16*)p_w0hi + (size_t)G * Din, (bf16*)p_w0lo + (size_t)G * Din,
                                  b_ih0 + G, b_hh0 + G,
                                  (float*)p_gx0 + (size_t)TT * Bsz * G, Bsz * TT, Din);

    // layer 0 bidirectional scan (tensor-core persistent)
    k_scan_mma<8, true><<<dim3(64, 2), 256>>>();

    // layer 1 fwd projection (A = o0 hi/lo straight from scan0) + bwd projection
    k_mma_gemm<<<gg, 256, MMSM>>>((bf16*)p_o0hi, (bf16*)p_o0lo,
                                  (bf16*)p_w1hi, (bf16*)p_w1lo,
                                  b_ih1, b_hh1, (float*)p_gx1f, Bsz * TT, 2 * Hh);
    k_mma_gemm<<<dim3(16, 1), 256, MMSM>>>(
        (bf16*)p_o0hi + (size_t)(TT - 1) * Bsz * 2 * Hh,
        (bf16*)p_o0lo + (size_t)(TT - 1) * Bsz * 2 * Hh,
        (bf16*)p_w1hi + (size_t)G * 2 * Hh, (bf16*)p_w1lo + (size_t)G * 2 * Hh,
        b_ih1 + G, b_hh1 + G, (float*)p_gx1b, Bsz, 2 * Hh);

    // layer 1 forward scan
    k_scan_mma<4, false><<<dim3(128, 1), 256>>>();

    k_l1bwd<<<128, 256>>>();
    k_head<<<64, 256>>>(ln_g, ln_b, w1, b1, w2, b2, out);
}